// round 5
// baseline (speedup 1.0000x reference)
#include <cuda_runtime.h>

#define NTHREADS 128
#define HID 32
#define NB 4
#define DIN 3

typedef unsigned long long ull;

// ---- scratch layout (floats), all of layers 0..2 pre-scaled by C=2*log2(e) ----
#define OFF_W0 0        // 384
#define OFF_B0 384      // 128
#define OFF_W1 512      // 4096
#define OFF_B1 4608     // 128
#define OFF_W2 4736     // 4096
#define OFF_B2 8832     // 128
#define OFF_W3 8960     // 128  (unscaled)
#define OFF_B3 9088     // 4    (unscaled)
#define SCRATCH_N 9092

__device__ float g_scaled[SCRATCH_N];

__constant__ float cW2[NB * HID * HID];
__constant__ float cb2[NB * HID];
__constant__ float cW3[NB * HID];
__constant__ float cb3[NB];

__device__ __forceinline__ ull fma2(ull a, ull b, ull c) {
    ull d; asm("fma.rn.f32x2 %0, %1, %2, %3;" : "=l"(d) : "l"(a), "l"(b), "l"(c)); return d;
}
__device__ __forceinline__ ull pack2(float lo, float hi) {
    ull r; asm("mov.b64 %0, {%1, %2};" : "=l"(r) : "f"(lo), "f"(hi)); return r;
}
__device__ __forceinline__ void unpack2(ull v, float& lo, float& hi) {
    asm("mov.b64 {%0, %1}, %2;" : "=f"(lo), "=f"(hi) : "l"(v));
}
__device__ __forceinline__ float ex2a(float x) {
    float y; asm("ex2.approx.f32 %0, %1;" : "=f"(y) : "f"(x)); return y;
}
__device__ __forceinline__ float rcpa(float x) {
    float y; asm("rcp.approx.f32 %0, %1;" : "=f"(y) : "f"(x)); return y;
}
// 16B load from __constant__ space (guaranteed const-port, not L1tex).
__device__ __forceinline__ void ldc2(const float* p, ull& a, ull& b) {
    asm("{ .reg .u64 t; cvta.to.const.u64 t, %2; ld.const.v2.u64 {%0,%1}, [t]; }"
        : "=l"(a), "=l"(b) : "l"(p));
}

// Weights/biases of layers 0..2 pre-scaled by C=2*log2(e): acc = C*z and
// tanh(z) = 1 - 2/(exp2(C*z)+1). Saturates correctly at +/-1.
__device__ __forceinline__ float tanh_pre(float a) {
    float y = ex2a(a);
    float r = rcpa(y + 1.0f);
    return fmaf(r, -2.0f, 1.0f);
}

// In-place 32->32 dense + tanh on packed hidden state hp[16], weights in SMEM.
__device__ __forceinline__ void dense32_smem(const float* __restrict__ w,
                                             const float* __restrict__ bias,
                                             ull* __restrict__ hp) {
    ull acc[16];
    const ulonglong2* bb = (const ulonglong2*)bias;
#pragma unroll
    for (int q = 0; q < 8; q++) {
        ulonglong2 t = bb[q];
        acc[2 * q] = t.x; acc[2 * q + 1] = t.y;
    }
#pragma unroll
    for (int j = 0; j < 16; j++) {
        float l, u; unpack2(hp[j], l, u);
        ull hl = pack2(l, l), hu = pack2(u, u);
        const ulonglong2* r0 = (const ulonglong2*)(w + (2 * j) * HID);
        const ulonglong2* r1 = (const ulonglong2*)(w + (2 * j + 1) * HID);
#pragma unroll
        for (int q = 0; q < 8; q++) {
            ulonglong2 w0 = r0[q];
            acc[2 * q]     = fma2(hl, w0.x, acc[2 * q]);
            acc[2 * q + 1] = fma2(hl, w0.y, acc[2 * q + 1]);
            ulonglong2 w1 = r1[q];
            acc[2 * q]     = fma2(hu, w1.x, acc[2 * q]);
            acc[2 * q + 1] = fma2(hu, w1.y, acc[2 * q + 1]);
        }
    }
#pragma unroll
    for (int j = 0; j < 16; j++) {
        float a, b; unpack2(acc[j], a, b);
        hp[j] = pack2(tanh_pre(a), tanh_pre(b));
    }
}

// In-place 32->32 dense + tanh, weights from __constant__ (const port).
__device__ __forceinline__ void dense32_const(const float* __restrict__ w,
                                              const float* __restrict__ bias,
                                              ull* __restrict__ hp) {
    ull acc[16];
#pragma unroll
    for (int q = 0; q < 8; q++) ldc2(bias + 4 * q, acc[2 * q], acc[2 * q + 1]);
#pragma unroll
    for (int j = 0; j < 16; j++) {
        float l, u; unpack2(hp[j], l, u);
        ull hl = pack2(l, l), hu = pack2(u, u);
        const float* r0 = w + (2 * j) * HID;
        const float* r1 = w + (2 * j + 1) * HID;
#pragma unroll
        for (int q = 0; q < 8; q++) {
            ull w0a, w0b; ldc2(r0 + 4 * q, w0a, w0b);
            acc[2 * q]     = fma2(hl, w0a, acc[2 * q]);
            acc[2 * q + 1] = fma2(hl, w0b, acc[2 * q + 1]);
            ull w1a, w1b; ldc2(r1 + 4 * q, w1a, w1b);
            acc[2 * q]     = fma2(hu, w1a, acc[2 * q]);
            acc[2 * q + 1] = fma2(hu, w1b, acc[2 * q + 1]);
        }
    }
#pragma unroll
    for (int j = 0; j < 16; j++) {
        float a, b; unpack2(acc[j], a, b);
        hp[j] = pack2(tanh_pre(a), tanh_pre(b));
    }
}

// ---- prescale: write C-scaled weights (layers 0..2) + raw layer 3 to scratch ----
__global__ void prescale_kernel(
    const float* __restrict__ W0, const float* __restrict__ b0,
    const float* __restrict__ W1, const float* __restrict__ b1,
    const float* __restrict__ W2, const float* __restrict__ b2,
    const float* __restrict__ W3, const float* __restrict__ b3) {
    const float C = 2.885390081777927f;
    int i = blockIdx.x * blockDim.x + threadIdx.x;
    int stride = gridDim.x * blockDim.x;
    for (; i < SCRATCH_N; i += stride) {
        float v;
        if (i < OFF_B0)       v = W0[i - OFF_W0] * C;
        else if (i < OFF_W1)  v = b0[i - OFF_B0] * C;
        else if (i < OFF_B1)  v = W1[i - OFF_W1] * C;
        else if (i < OFF_W2)  v = b1[i - OFF_B1] * C;
        else if (i < OFF_B2)  v = W2[i - OFF_W2] * C;
        else if (i < OFF_W3)  v = b2[i - OFF_B2] * C;
        else if (i < OFF_B3)  v = W3[i - OFF_W3];
        else                  v = b3[i - OFF_B3];
        g_scaled[i] = v;
    }
}

__global__ void __launch_bounds__(NTHREADS, 5) pfnn_kernel(
    const float* __restrict__ x, float* __restrict__ out, int n) {
    __shared__ __align__(16) float sW0[NB][DIN][HID];
    __shared__ __align__(16) float sb0[NB][HID];
    __shared__ __align__(16) float sW1[NB][HID][HID];
    __shared__ __align__(16) float sb1[NB][HID];

    const int tid = threadIdx.x;
    {
        const float4* src = (const float4*)(g_scaled + OFF_W1);
        float4* dst = (float4*)&sW1[0][0][0];
        for (int i = tid; i < NB * HID * HID / 4; i += NTHREADS) dst[i] = src[i];
        for (int i = tid; i < NB * DIN * HID; i += NTHREADS)
            (&sW0[0][0][0])[i] = g_scaled[OFF_W0 + i];
        for (int i = tid; i < NB * HID; i += NTHREADS) {
            (&sb0[0][0])[i] = g_scaled[OFF_B0 + i];
            (&sb1[0][0])[i] = g_scaled[OFF_B1 + i];
        }
    }
    __syncthreads();

    const int idx = blockIdx.x * NTHREADS + tid;
    if (idx >= n) return;

    const float x0 = x[idx * 3 + 0];
    const float x1 = x[idx * 3 + 1];
    const float x2 = x[idx * 3 + 2];
    const ull xx0 = pack2(x0, x0);
    const ull xx1 = pack2(x1, x1);
    const ull xx2 = pack2(x2, x2);

    float o[NB];

#pragma unroll 1
    for (int b = 0; b < NB; ++b) {
        // ---- layer 0: 3 -> 32, tanh (smem, pre-scaled) ----
        ull hp[16];
        {
            ull acc[16];
            const ulonglong2* bb = (const ulonglong2*)sb0[b];
#pragma unroll
            for (int q = 0; q < 8; q++) {
                ulonglong2 t = bb[q];
                acc[2 * q] = t.x; acc[2 * q + 1] = t.y;
            }
            const ulonglong2* w0r = (const ulonglong2*)sW0[b][0];
            const ulonglong2* w1r = (const ulonglong2*)sW0[b][1];
            const ulonglong2* w2r = (const ulonglong2*)sW0[b][2];
#pragma unroll
            for (int q = 0; q < 8; q++) {
                ulonglong2 wv0 = w0r[q];
                acc[2 * q]     = fma2(xx0, wv0.x, acc[2 * q]);
                acc[2 * q + 1] = fma2(xx0, wv0.y, acc[2 * q + 1]);
                ulonglong2 wv1 = w1r[q];
                acc[2 * q]     = fma2(xx1, wv1.x, acc[2 * q]);
                acc[2 * q + 1] = fma2(xx1, wv1.y, acc[2 * q + 1]);
                ulonglong2 wv2 = w2r[q];
                acc[2 * q]     = fma2(xx2, wv2.x, acc[2 * q]);
                acc[2 * q + 1] = fma2(xx2, wv2.y, acc[2 * q + 1]);
            }
#pragma unroll
            for (int j = 0; j < 16; j++) {
                float a, c; unpack2(acc[j], a, c);
                hp[j] = pack2(tanh_pre(a), tanh_pre(c));
            }
        }

        // ---- layer 1: smem ---- layer 2: constant port ----
        dense32_smem(&sW1[b][0][0], sb1[b], hp);
        dense32_const(&cW2[b * HID * HID], &cb2[b * HID], hp);

        // ---- layer 3: 32 -> 1 (constant, unscaled) ----
        {
            const float* w3 = &cW3[b * HID];
            ull s = pack2(0.0f, 0.0f);
#pragma unroll
            for (int q = 0; q < 8; q++) {
                ull wa, wb; ldc2(w3 + 4 * q, wa, wb);
                s = fma2(hp[2 * q],     wa, s);
                s = fma2(hp[2 * q + 1], wb, s);
            }
            float a, c; unpack2(s, a, c);
            o[b] = cb3[b] + a + c;
        }
    }

    ((float4*)out)[idx] = make_float4(o[0], o[1], o[2], o[3]);
}

extern "C" void kernel_launch(void* const* d_in, const int* in_sizes, int n_in,
                              void* d_out, int out_size) {
    const float* x  = (const float*)d_in[0];
    const float* W0 = (const float*)d_in[1];
    const float* b0 = (const float*)d_in[2];
    const float* W1 = (const float*)d_in[3];
    const float* b1 = (const float*)d_in[4];
    const float* W2 = (const float*)d_in[5];
    const float* b2 = (const float*)d_in[6];
    const float* W3 = (const float*)d_in[7];
    const float* b3 = (const float*)d_in[8];
    float* out = (float*)d_out;

    const int n = in_sizes[0] / 3;

    // 1) scale weights into device scratch
    prescale_kernel<<<16, 256>>>(W0, b0, W1, b1, W2, b2, W3, b3);

    // 2) fill constant bank for layers 2,3 (D2D memcpy nodes; capture-legal)
    void* sp = nullptr;
    cudaGetSymbolAddress(&sp, g_scaled);
    const float* s = (const float*)sp;
    cudaMemcpyToSymbolAsync(cW2, s + OFF_W2, NB * HID * HID * sizeof(float), 0,
                            cudaMemcpyDeviceToDevice, 0);
    cudaMemcpyToSymbolAsync(cb2, s + OFF_B2, NB * HID * sizeof(float), 0,
                            cudaMemcpyDeviceToDevice, 0);
    cudaMemcpyToSymbolAsync(cW3, s + OFF_W3, NB * HID * sizeof(float), 0,
                            cudaMemcpyDeviceToDevice, 0);
    cudaMemcpyToSymbolAsync(cb3, s + OFF_B3, NB * sizeof(float), 0,
                            cudaMemcpyDeviceToDevice, 0);

    // 3) main kernel
    const int blocks = (n + NTHREADS - 1) / NTHREADS;
    pfnn_kernel<<<blocks, NTHREADS>>>(x, out, n);
}

// round 9
// speedup vs baseline: 2.2878x; 2.2878x over previous
#include <cuda_runtime.h>
#include <cuda_bf16.h>
#include <cstdint>

#define NT 128
#define HID 32
#define NB 4

// ---------------- device-global prebuilt parameter buffers ----------------
// B fragments for layers 1,2 in exact mma.m16n8k16 B-fragment order:
// index [l][b][kt][nt][lane] -> uint2 {reg0 (k=kt*16+tid*2+{0,1}), reg1 (+8)}
__device__ uint2  gFragHi[2 * NB * 2 * 4 * 32];
__device__ uint2  gFragLo[2 * NB * 2 * 4 * 32];
__device__ float4 gW04[NB * HID];      // (C*W0[0][j], C*W0[1][j], C*W0[2][j], C*b0[j])
__device__ float  gBias12[2 * NB * HID];  // C*b1, C*b2
__device__ float  gW3v[NB * HID];
__device__ float  gb3v[NB];

// ---------------- helpers ----------------
__device__ __forceinline__ float ex2a(float x) {
    float y; asm("ex2.approx.f32 %0, %1;" : "=f"(y) : "f"(x)); return y;
}
__device__ __forceinline__ float rcpa(float x) {
    float y; asm("rcp.approx.f32 %0, %1;" : "=f"(y) : "f"(x)); return y;
}
// Arg pre-scaled by C=2*log2(e): tanh(z) = 1 - 2/(exp2(C*z)+1). Saturates at +/-1.
__device__ __forceinline__ float tanh_pre(float a) {
    float y = ex2a(a);
    float r = rcpa(y + 1.0f);
    return fmaf(r, -2.0f, 1.0f);
}
// pack two f32 -> bf16x2 word, LOW half = first arg
__device__ __forceinline__ uint32_t cvt2(float lo, float hi) {
    uint32_t d; asm("cvt.rn.bf16x2.f32 %0, %1, %2;" : "=r"(d) : "f"(hi), "f"(lo)); return d;
}
__device__ __forceinline__ void mma_bf16(float* c, const uint32_t* a, uint2 b) {
    asm volatile(
        "mma.sync.aligned.m16n8k16.row.col.f32.bf16.bf16.f32 "
        "{%0,%1,%2,%3}, {%4,%5,%6,%7}, {%8,%9}, {%0,%1,%2,%3};"
        : "+f"(c[0]), "+f"(c[1]), "+f"(c[2]), "+f"(c[3])
        : "r"(a[0]), "r"(a[1]), "r"(a[2]), "r"(a[3]), "r"(b.x), "r"(b.y));
}

// C fragments (2 mtiles x 4 ntiles x 4 f32) -> A fragments hi/lo [mt][kt][4]
// Identity: A(m16k16) of ktile kt = [C_tile(nt=2kt) | C_tile(nt=2kt+1)]
__device__ __forceinline__ void conv_A(const float Cc[2][4][4],
                                       uint32_t Ah[2][2][4], uint32_t Al[2][2][4]) {
#pragma unroll
    for (int mt = 0; mt < 2; mt++)
#pragma unroll
        for (int kt = 0; kt < 2; kt++)
#pragma unroll
            for (int i = 0; i < 2; i++) {
                const float* cf = Cc[mt][2 * kt + i];
                uint32_t h0 = cvt2(cf[0], cf[1]);
                uint32_t h1 = cvt2(cf[2], cf[3]);
                float r00 = cf[0] - __uint_as_float(h0 << 16);
                float r01 = cf[1] - __uint_as_float(h0 & 0xffff0000u);
                float r10 = cf[2] - __uint_as_float(h1 << 16);
                float r11 = cf[3] - __uint_as_float(h1 & 0xffff0000u);
                Ah[mt][kt][2 * i]     = h0;
                Ah[mt][kt][2 * i + 1] = h1;
                Al[mt][kt][2 * i]     = cvt2(r00, r01);
                Al[mt][kt][2 * i + 1] = cvt2(r10, r11);
            }
}

// ---------------- prep kernel: build fragments + scaled params ----------------
__global__ void prep_kernel(
    const float* __restrict__ W0, const float* __restrict__ b0,
    const float* __restrict__ W1, const float* __restrict__ b1,
    const float* __restrict__ W2, const float* __restrict__ b2,
    const float* __restrict__ W3, const float* __restrict__ b3) {
    const float C = 2.885390081777927f;  // 2*log2(e)
    const int gsz = gridDim.x * blockDim.x;
    int i0 = blockIdx.x * blockDim.x + threadIdx.x;

    // B fragments: 2048 uint2 entries, each holds 2 regs (4 bf16) hi + lo
    for (int f = i0; f < 2 * NB * 2 * 4 * 32; f += gsz) {
        int lane = f & 31;
        int nt = (f >> 5) & 3;
        int kt = (f >> 7) & 1;
        int b  = (f >> 8) & 3;
        int l  = (f >> 10) & 1;
        int g = lane >> 2, tid4 = lane & 3;
        int n = nt * 8 + g;
        const float* src = l ? W2 : W1;
        uint32_t hw[2], lw[2];
#pragma unroll
        for (int r = 0; r < 2; r++) {
            int k0 = kt * 16 + tid4 * 2 + r * 8;
            float v0 = src[b * 1024 + k0 * 32 + n] * C;
            float v1 = src[b * 1024 + (k0 + 1) * 32 + n] * C;
            uint32_t h = cvt2(v0, v1);
            float r0 = v0 - __uint_as_float(h << 16);
            float r1 = v1 - __uint_as_float(h & 0xffff0000u);
            hw[r] = h;
            lw[r] = cvt2(r0, r1);
        }
        gFragHi[f] = make_uint2(hw[0], hw[1]);
        gFragLo[f] = make_uint2(lw[0], lw[1]);
    }
    // layer0 coefficients
    for (int i = i0; i < NB * HID; i += gsz) {
        int b = i >> 5, j = i & 31;
        gW04[i] = make_float4(W0[b * 96 + 0 * 32 + j] * C,
                              W0[b * 96 + 1 * 32 + j] * C,
                              W0[b * 96 + 2 * 32 + j] * C,
                              b0[i] * C);
        gW3v[i] = W3[i];
    }
    for (int i = i0; i < 2 * NB * HID; i += gsz) {
        int l = i >> 7;
        int r = i & 127;
        gBias12[i] = (l ? b2[r] : b1[r]) * C;
    }
    if (i0 < NB) gb3v[i0] = b3[i0];
}

// ---------------- main kernel ----------------
__global__ void __launch_bounds__(NT, 3) pfnn_mma(
    const float* __restrict__ x, float* __restrict__ out, int n) {
    __shared__ uint2  sFH[2 * NB * 2 * 4 * 32];
    __shared__ uint2  sFL[2 * NB * 2 * 4 * 32];
    __shared__ float4 sW04[NB * HID];
    __shared__ float  sB12[2 * NB * HID];
    __shared__ float  sW3s[NB * HID];
    __shared__ float  sb3s[NB];

    const int tidx = threadIdx.x;
    for (int i = tidx; i < 2048; i += NT) { sFH[i] = gFragHi[i]; sFL[i] = gFragLo[i]; }
    for (int i = tidx; i < NB * HID; i += NT) { sW04[i] = gW04[i]; sW3s[i] = gW3v[i]; }
    for (int i = tidx; i < 2 * NB * HID; i += NT) sB12[i] = gBias12[i];
    if (tidx < NB) sb3s[tidx] = gb3v[tidx];
    __syncthreads();

    const int wid = tidx >> 5;
    const int lane = tidx & 31;
    const int g = lane >> 2, tid4 = lane & 3;
    const int warpstart = blockIdx.x * NT + wid * 32;

    // this lane's point (for x distribution only)
    int p = warpstart + lane;
    int pc = (p < n) ? p : (n - 1);
    float mx0 = x[3 * pc], mx1 = x[3 * pc + 1], mx2 = x[3 * pc + 2];

    // x of the 4 rows this thread owns: q = mt*2 + h, row = mt*16 + g + 8h
    float rx[4], ry[4], rz[4];
#pragma unroll
    for (int q = 0; q < 4; q++) {
        int src = ((q >> 1) << 4) + g + ((q & 1) << 3);
        rx[q] = __shfl_sync(0xffffffffu, mx0, src);
        ry[q] = __shfl_sync(0xffffffffu, mx1, src);
        rz[q] = __shfl_sync(0xffffffffu, mx2, src);
    }

    float obuf[4] = {0.f, 0.f, 0.f, 0.f};

#pragma unroll 1
    for (int b = 0; b < NB; b++) {
        float Cc[2][4][4];

        // ---- layer 0: 3 -> 32 directly in C-fragment layout ----
#pragma unroll
        for (int nt = 0; nt < 4; nt++) {
            int j0 = nt * 8 + 2 * tid4;
            float4 q0 = sW04[b * HID + j0];
            float4 q1 = sW04[b * HID + j0 + 1];
#pragma unroll
            for (int mt = 0; mt < 2; mt++) {
                float za = fmaf(rx[mt * 2], q0.x, fmaf(ry[mt * 2], q0.y, fmaf(rz[mt * 2], q0.z, q0.w)));
                float zb = fmaf(rx[mt * 2], q1.x, fmaf(ry[mt * 2], q1.y, fmaf(rz[mt * 2], q1.z, q1.w)));
                float zc = fmaf(rx[mt * 2 + 1], q0.x, fmaf(ry[mt * 2 + 1], q0.y, fmaf(rz[mt * 2 + 1], q0.z, q0.w)));
                float zd = fmaf(rx[mt * 2 + 1], q1.x, fmaf(ry[mt * 2 + 1], q1.y, fmaf(rz[mt * 2 + 1], q1.z, q1.w)));
                Cc[mt][nt][0] = tanh_pre(za);
                Cc[mt][nt][1] = tanh_pre(zb);
                Cc[mt][nt][2] = tanh_pre(zc);
                Cc[mt][nt][3] = tanh_pre(zd);
            }
        }

        uint32_t Ah[2][2][4], Al[2][2][4];
        conv_A(Cc, Ah, Al);

        // ---- layers 1,2: tensor-core 32x32 with 3-pass split-bf16 ----
#pragma unroll 1
        for (int l = 0; l < 2; l++) {
            uint2 Bh[2][4], Bl[2][4];
            int fbase = ((l * NB + b) * 2) * 4 * 32;
#pragma unroll
            for (int kt = 0; kt < 2; kt++)
#pragma unroll
                for (int nt = 0; nt < 4; nt++) {
                    int fi = fbase + (kt * 4 + nt) * 32 + lane;
                    Bh[kt][nt] = sFH[fi];
                    Bl[kt][nt] = sFL[fi];
                }
            // init C with (scaled) bias
#pragma unroll
            for (int nt = 0; nt < 4; nt++) {
                float v0 = sB12[(l * NB + b) * HID + nt * 8 + 2 * tid4];
                float v1 = sB12[(l * NB + b) * HID + nt * 8 + 2 * tid4 + 1];
#pragma unroll
                for (int mt = 0; mt < 2; mt++) {
                    Cc[mt][nt][0] = v0; Cc[mt][nt][1] = v1;
                    Cc[mt][nt][2] = v0; Cc[mt][nt][3] = v1;
                }
            }
            // mma: hi*hi + lo*hi + hi*lo over 2 k-tiles
#pragma unroll
            for (int mt = 0; mt < 2; mt++)
#pragma unroll
                for (int nt = 0; nt < 4; nt++) {
                    mma_bf16(Cc[mt][nt], Ah[mt][0], Bh[0][nt]);
                    mma_bf16(Cc[mt][nt], Ah[mt][1], Bh[1][nt]);
                    mma_bf16(Cc[mt][nt], Al[mt][0], Bh[0][nt]);
                    mma_bf16(Cc[mt][nt], Al[mt][1], Bh[1][nt]);
                    mma_bf16(Cc[mt][nt], Ah[mt][0], Bl[0][nt]);
                    mma_bf16(Cc[mt][nt], Ah[mt][1], Bl[1][nt]);
                }
            // tanh
#pragma unroll
            for (int mt = 0; mt < 2; mt++)
#pragma unroll
                for (int nt = 0; nt < 4; nt++)
#pragma unroll
                    for (int e = 0; e < 4; e++)
                        Cc[mt][nt][e] = tanh_pre(Cc[mt][nt][e]);

            if (l == 0) conv_A(Cc, Ah, Al);
        }

        // ---- layer 3: 32 -> 1, butterfly reduce across the 4-lane group ----
        float s[4] = {0.f, 0.f, 0.f, 0.f};
#pragma unroll
        for (int nt = 0; nt < 4; nt++) {
            float w0 = sW3s[b * HID + nt * 8 + 2 * tid4];
            float w1 = sW3s[b * HID + nt * 8 + 2 * tid4 + 1];
#pragma unroll
            for (int mt = 0; mt < 2; mt++) {
                s[mt * 2 + 0] = fmaf(Cc[mt][nt][0], w0, fmaf(Cc[mt][nt][1], w1, s[mt * 2 + 0]));
                s[mt * 2 + 1] = fmaf(Cc[mt][nt][2], w0, fmaf(Cc[mt][nt][3], w1, s[mt * 2 + 1]));
            }
        }
#pragma unroll
        for (int q = 0; q < 4; q++) {
            s[q] += __shfl_xor_sync(0xffffffffu, s[q], 1);
            s[q] += __shfl_xor_sync(0xffffffffu, s[q], 2);
        }
        if (tid4 == b) {
#pragma unroll
            for (int q = 0; q < 4; q++) obuf[q] = s[q] + sb3s[b];
        }
    }

    // ---- store: lane group (tid4=0..3) writes 4 consecutive branch floats of each row ----
#pragma unroll
    for (int q = 0; q < 4; q++) {
        int row = ((q >> 1) << 4) + g + ((q & 1) << 3);
        int pp = warpstart + row;
        if (pp < n) out[pp * 4 + tid4] = obuf[q];
    }
}

extern "C" void kernel_launch(void* const* d_in, const int* in_sizes, int n_in,
                              void* d_out, int out_size) {
    const float* x  = (const float*)d_in[0];
    const float* W0 = (const float*)d_in[1];
    const float* b0 = (const float*)d_in[2];
    const float* W1 = (const float*)d_in[3];
    const float* b1 = (const float*)d_in[4];
    const float* W2 = (const float*)d_in[5];
    const float* b2 = (const float*)d_in[6];
    const float* W3 = (const float*)d_in[7];
    const float* b3 = (const float*)d_in[8];
    float* out = (float*)d_out;

    const int n = in_sizes[0] / 3;

    prep_kernel<<<8, 256>>>(W0, b0, W1, b1, W2, b2, W3, b3);

    const int blocks = (n + NT - 1) / NT;
    pfnn_mma<<<blocks, NT>>>(x, out, n);
}

// round 11
// speedup vs baseline: 3.6274x; 1.5856x over previous
#include <cuda_runtime.h>
#include <cuda_bf16.h>
#include <cstdint>

#define NT 128
#define HID 32
#define NB 4

// ---------------- device-global prebuilt parameter buffers ----------------
// B fragments for layers 1,2 in exact mma.m16n8k16 B-fragment order:
// index [l][b][kt][nt][lane] -> uint2 {reg0 (k=kt*16+tid*2+{0,1}), reg1 (+8)}
__device__ uint2  gFragHi[2 * NB * 2 * 4 * 32];
__device__ uint2  gFragLo[2 * NB * 2 * 4 * 32];
__device__ float4 gW04[NB * HID];      // (W0[0][j], W0[1][j], W0[2][j], b0[j])
__device__ float  gBias12[2 * NB * HID];  // b1, b2
__device__ float  gW3v[NB * HID];
__device__ float  gb3v[NB];

// ---------------- helpers ----------------
// Single-MUFU tanh (sm_75+). Max abs err ~6e-4, RMS ~2e-4 — well under 1e-3 gate
// given measured error scaling from R6 (bf16-GEMM 1e-5 activ err -> 2.9e-6 rel_err).
__device__ __forceinline__ float tanha(float z) {
    float y; asm("tanh.approx.f32 %0, %1;" : "=f"(y) : "f"(z)); return y;
}
// pack two f32 -> bf16x2 word, LOW half = first arg
__device__ __forceinline__ uint32_t cvt2(float lo, float hi) {
    uint32_t d; asm("cvt.rn.bf16x2.f32 %0, %1, %2;" : "=r"(d) : "f"(hi), "f"(lo)); return d;
}
__device__ __forceinline__ void mma_bf16(float* c, const uint32_t* a, uint2 b) {
    asm volatile(
        "mma.sync.aligned.m16n8k16.row.col.f32.bf16.bf16.f32 "
        "{%0,%1,%2,%3}, {%4,%5,%6,%7}, {%8,%9}, {%0,%1,%2,%3};"
        : "+f"(c[0]), "+f"(c[1]), "+f"(c[2]), "+f"(c[3])
        : "r"(a[0]), "r"(a[1]), "r"(a[2]), "r"(a[3]), "r"(b.x), "r"(b.y));
}

// C fragments (2 mtiles x 4 ntiles x 4 f32) -> A fragments hi/lo [mt][kt][4]
// Identity: A(m16k16) of ktile kt = [C_tile(nt=2kt) | C_tile(nt=2kt+1)]
__device__ __forceinline__ void conv_A(const float Cc[2][4][4],
                                       uint32_t Ah[2][2][4], uint32_t Al[2][2][4]) {
#pragma unroll
    for (int mt = 0; mt < 2; mt++)
#pragma unroll
        for (int kt = 0; kt < 2; kt++)
#pragma unroll
            for (int i = 0; i < 2; i++) {
                const float* cf = Cc[mt][2 * kt + i];
                uint32_t h0 = cvt2(cf[0], cf[1]);
                uint32_t h1 = cvt2(cf[2], cf[3]);
                float r00 = cf[0] - __uint_as_float(h0 << 16);
                float r01 = cf[1] - __uint_as_float(h0 & 0xffff0000u);
                float r10 = cf[2] - __uint_as_float(h1 << 16);
                float r11 = cf[3] - __uint_as_float(h1 & 0xffff0000u);
                Ah[mt][kt][2 * i]     = h0;
                Ah[mt][kt][2 * i + 1] = h1;
                Al[mt][kt][2 * i]     = cvt2(r00, r01);
                Al[mt][kt][2 * i + 1] = cvt2(r10, r11);
            }
}

// ---------------- prep kernel: build fragments + params (no scaling) ----------------
__global__ void prep_kernel(
    const float* __restrict__ W0, const float* __restrict__ b0,
    const float* __restrict__ W1, const float* __restrict__ b1,
    const float* __restrict__ W2, const float* __restrict__ b2,
    const float* __restrict__ W3, const float* __restrict__ b3) {
    const int gsz = gridDim.x * blockDim.x;
    int i0 = blockIdx.x * blockDim.x + threadIdx.x;

    // B fragments: 2048 uint2 entries, each holds 2 regs (4 bf16) hi + lo
    for (int f = i0; f < 2 * NB * 2 * 4 * 32; f += gsz) {
        int lane = f & 31;
        int nt = (f >> 5) & 3;
        int kt = (f >> 7) & 1;
        int b  = (f >> 8) & 3;
        int l  = (f >> 10) & 1;
        int g = lane >> 2, tid4 = lane & 3;
        int n = nt * 8 + g;
        const float* src = l ? W2 : W1;
        uint32_t hw[2], lw[2];
#pragma unroll
        for (int r = 0; r < 2; r++) {
            int k0 = kt * 16 + tid4 * 2 + r * 8;
            float v0 = src[b * 1024 + k0 * 32 + n];
            float v1 = src[b * 1024 + (k0 + 1) * 32 + n];
            uint32_t h = cvt2(v0, v1);
            float r0 = v0 - __uint_as_float(h << 16);
            float r1 = v1 - __uint_as_float(h & 0xffff0000u);
            hw[r] = h;
            lw[r] = cvt2(r0, r1);
        }
        gFragHi[f] = make_uint2(hw[0], hw[1]);
        gFragLo[f] = make_uint2(lw[0], lw[1]);
    }
    // layer0 coefficients
    for (int i = i0; i < NB * HID; i += gsz) {
        int b = i >> 5, j = i & 31;
        gW04[i] = make_float4(W0[b * 96 + 0 * 32 + j],
                              W0[b * 96 + 1 * 32 + j],
                              W0[b * 96 + 2 * 32 + j],
                              b0[i]);
        gW3v[i] = W3[i];
    }
    for (int i = i0; i < 2 * NB * HID; i += gsz) {
        int l = i >> 7;
        int r = i & 127;
        gBias12[i] = l ? b2[r] : b1[r];
    }
    if (i0 < NB) gb3v[i0] = b3[i0];
}

// ---------------- main kernel ----------------
__global__ void __launch_bounds__(NT, 3) pfnn_mma(
    const float* __restrict__ x, float* __restrict__ out, int n) {
    __shared__ uint2  sFH[2 * NB * 2 * 4 * 32];
    __shared__ uint2  sFL[2 * NB * 2 * 4 * 32];
    __shared__ float4 sW04[NB * HID];
    __shared__ float  sB12[2 * NB * HID];
    __shared__ float  sW3s[NB * HID];
    __shared__ float  sb3s[NB];

    const int tidx = threadIdx.x;
    for (int i = tidx; i < 2048; i += NT) { sFH[i] = gFragHi[i]; sFL[i] = gFragLo[i]; }
    for (int i = tidx; i < NB * HID; i += NT) { sW04[i] = gW04[i]; sW3s[i] = gW3v[i]; }
    for (int i = tidx; i < 2 * NB * HID; i += NT) sB12[i] = gBias12[i];
    if (tidx < NB) sb3s[tidx] = gb3v[tidx];
    __syncthreads();

    const int wid = tidx >> 5;
    const int lane = tidx & 31;
    const int g = lane >> 2, tid4 = lane & 3;
    const int warpstart = blockIdx.x * NT + wid * 32;

    // this lane's point (for x distribution only)
    int p = warpstart + lane;
    int pc = (p < n) ? p : (n - 1);
    float mx0 = x[3 * pc], mx1 = x[3 * pc + 1], mx2 = x[3 * pc + 2];

    // x of the 4 rows this thread owns: q = mt*2 + h, row = mt*16 + g + 8h
    float rx[4], ry[4], rz[4];
#pragma unroll
    for (int q = 0; q < 4; q++) {
        int src = ((q >> 1) << 4) + g + ((q & 1) << 3);
        rx[q] = __shfl_sync(0xffffffffu, mx0, src);
        ry[q] = __shfl_sync(0xffffffffu, mx1, src);
        rz[q] = __shfl_sync(0xffffffffu, mx2, src);
    }

    float obuf[4] = {0.f, 0.f, 0.f, 0.f};

#pragma unroll 1
    for (int b = 0; b < NB; b++) {
        float Cc[2][4][4];

        // ---- layer 0: 3 -> 32 directly in C-fragment layout ----
#pragma unroll
        for (int nt = 0; nt < 4; nt++) {
            int j0 = nt * 8 + 2 * tid4;
            float4 q0 = sW04[b * HID + j0];
            float4 q1 = sW04[b * HID + j0 + 1];
#pragma unroll
            for (int mt = 0; mt < 2; mt++) {
                float za = fmaf(rx[mt * 2], q0.x, fmaf(ry[mt * 2], q0.y, fmaf(rz[mt * 2], q0.z, q0.w)));
                float zb = fmaf(rx[mt * 2], q1.x, fmaf(ry[mt * 2], q1.y, fmaf(rz[mt * 2], q1.z, q1.w)));
                float zc = fmaf(rx[mt * 2 + 1], q0.x, fmaf(ry[mt * 2 + 1], q0.y, fmaf(rz[mt * 2 + 1], q0.z, q0.w)));
                float zd = fmaf(rx[mt * 2 + 1], q1.x, fmaf(ry[mt * 2 + 1], q1.y, fmaf(rz[mt * 2 + 1], q1.z, q1.w)));
                Cc[mt][nt][0] = tanha(za);
                Cc[mt][nt][1] = tanha(zb);
                Cc[mt][nt][2] = tanha(zc);
                Cc[mt][nt][3] = tanha(zd);
            }
        }

        uint32_t Ah[2][2][4], Al[2][2][4];
        conv_A(Cc, Ah, Al);

        // ---- layers 1,2: tensor-core 32x32 with 3-pass split-bf16 ----
#pragma unroll 1
        for (int l = 0; l < 2; l++) {
            uint2 Bh[2][4], Bl[2][4];
            int fbase = ((l * NB + b) * 2) * 4 * 32;
#pragma unroll
            for (int kt = 0; kt < 2; kt++)
#pragma unroll
                for (int nt = 0; nt < 4; nt++) {
                    int fi = fbase + (kt * 4 + nt) * 32 + lane;
                    Bh[kt][nt] = sFH[fi];
                    Bl[kt][nt] = sFL[fi];
                }
            // init C with bias
#pragma unroll
            for (int nt = 0; nt < 4; nt++) {
                float v0 = sB12[(l * NB + b) * HID + nt * 8 + 2 * tid4];
                float v1 = sB12[(l * NB + b) * HID + nt * 8 + 2 * tid4 + 1];
#pragma unroll
                for (int mt = 0; mt < 2; mt++) {
                    Cc[mt][nt][0] = v0; Cc[mt][nt][1] = v1;
                    Cc[mt][nt][2] = v0; Cc[mt][nt][3] = v1;
                }
            }
            // mma: hi*hi + lo*hi + hi*lo over 2 k-tiles
#pragma unroll
            for (int mt = 0; mt < 2; mt++)
#pragma unroll
                for (int nt = 0; nt < 4; nt++) {
                    mma_bf16(Cc[mt][nt], Ah[mt][0], Bh[0][nt]);
                    mma_bf16(Cc[mt][nt], Ah[mt][1], Bh[1][nt]);
                    mma_bf16(Cc[mt][nt], Al[mt][0], Bh[0][nt]);
                    mma_bf16(Cc[mt][nt], Al[mt][1], Bh[1][nt]);
                    mma_bf16(Cc[mt][nt], Ah[mt][0], Bl[0][nt]);
                    mma_bf16(Cc[mt][nt], Ah[mt][1], Bl[1][nt]);
                }
            // tanh (single MUFU per element)
#pragma unroll
            for (int mt = 0; mt < 2; mt++)
#pragma unroll
                for (int nt = 0; nt < 4; nt++)
#pragma unroll
                    for (int e = 0; e < 4; e++)
                        Cc[mt][nt][e] = tanha(Cc[mt][nt][e]);

            if (l == 0) conv_A(Cc, Ah, Al);
        }

        // ---- layer 3: 32 -> 1, butterfly reduce across the 4-lane group ----
        float s[4] = {0.f, 0.f, 0.f, 0.f};
#pragma unroll
        for (int nt = 0; nt < 4; nt++) {
            float w0 = sW3s[b * HID + nt * 8 + 2 * tid4];
            float w1 = sW3s[b * HID + nt * 8 + 2 * tid4 + 1];
#pragma unroll
            for (int mt = 0; mt < 2; mt++) {
                s[mt * 2 + 0] = fmaf(Cc[mt][nt][0], w0, fmaf(Cc[mt][nt][1], w1, s[mt * 2 + 0]));
                s[mt * 2 + 1] = fmaf(Cc[mt][nt][2], w0, fmaf(Cc[mt][nt][3], w1, s[mt * 2 + 1]));
            }
        }
#pragma unroll
        for (int q = 0; q < 4; q++) {
            s[q] += __shfl_xor_sync(0xffffffffu, s[q], 1);
            s[q] += __shfl_xor_sync(0xffffffffu, s[q], 2);
        }
        if (tid4 == b) {
#pragma unroll
            for (int q = 0; q < 4; q++) obuf[q] = s[q] + sb3s[b];
        }
    }

    // ---- store: lane group (tid4=0..3) writes 4 consecutive branch floats of each row ----
#pragma unroll
    for (int q = 0; q < 4; q++) {
        int row = ((q >> 1) << 4) + g + ((q & 1) << 3);
        int pp = warpstart + row;
        if (pp < n) out[pp * 4 + tid4] = obuf[q];
    }
}

extern "C" void kernel_launch(void* const* d_in, const int* in_sizes, int n_in,
                              void* d_out, int out_size) {
    const float* x  = (const float*)d_in[0];
    const float* W0 = (const float*)d_in[1];
    const float* b0 = (const float*)d_in[2];
    const float* W1 = (const float*)d_in[3];
    const float* b1 = (const float*)d_in[4];
    const float* W2 = (const float*)d_in[5];
    const float* b2 = (const float*)d_in[6];
    const float* W3 = (const float*)d_in[7];
    const float* b3 = (const float*)d_in[8];
    float* out = (float*)d_out;

    const int n = in_sizes[0] / 3;

    prep_kernel<<<8, 256>>>(W0, b0, W1, b1, W2, b2, W3, b3);

    const int blocks = (n + NT - 1) / NT;
    pfnn_mma<<<blocks, NT>>>(x, out, n);
}